// round 7
// baseline (speedup 1.0000x reference)
#include <cuda_runtime.h>
#include <cuda_bf16.h>

// Problem shape (fixed for this bench problem)
#define SEQ  1024
#define BAT  512
#define NTAG 64
#define TSTRIDE (BAT * NTAG)
#define LN2 0.69314718055994531f

typedef unsigned long long ull;

// Scratch (device globals: allocation-free rule)
__device__ float g_denom[BAT];
__device__ float g_score[BAT];
__device__ int   g_maskT[BAT * SEQ];
__device__ int   g_tags_is64;
__device__ int   g_mask_ones;

// ---------------------------------------------------------------------------
__global__ void detect_tags_kernel(const int* __restrict__ tags32) {
    int is64 = 1;
    for (int i = 1; i < 128; i += 2)
        if (tags32[i] != 0) { is64 = 0; break; }
    g_tags_is64 = is64;
    g_mask_ones = 1;
}

__device__ __forceinline__ int load_tag(const void* tags, size_t idx, int is64) {
    if (is64) return (int)((const long long*)tags)[idx];
    return ((const int*)tags)[idx];
}

// ---------------------------------------------------------------------------
__global__ void mask_transpose_kernel(const int* __restrict__ mask) {
    int idx = blockIdx.x * blockDim.x + threadIdx.x;
    if (idx < SEQ * BAT) {
        int t = idx / BAT;
        int b = idx - t * BAT;
        int v = mask[idx];
        g_maskT[b * SEQ + t] = v;
        if (v != 1) g_mask_ones = 0;   // benign race: all writers store 0
    }
}

// ---------------------------------------------------------------------------
// One linear-space step, single warp, 2 columns per thread (fast path).
// Reads all 64 s-values (broadcast LDS), computes dots for cols 2l, 2l+1.
// Returns new pair; updates s0prev (lane-0 col-0 value) via shfl.
// ---------------------------------------------------------------------------
__device__ __forceinline__ void fast_step_w(
    const float* __restrict__ se_read, float* __restrict__ se_write, int l,
    const ull* __restrict__ Ep0, const ull* __restrict__ Ep1,
    float2 raw, float& s0prev, int& e_sum)
{
    const float ca = __expf(raw.x);   // MUFU, hidden under the dot
    const float cb = __expf(raw.y);

    // renorm scale from s0prev (exact power of 2) — off critical path
    int ex = (__float_as_int(s0prev) >> 23) & 0xFF;
    ex = max(1, min(ex, 253));
    e_sum += ex - 127;
    const float rsc = __int_as_float((254 - ex) << 23);
    const float ma = ca * rsc;
    const float mb = cb * rsc;

    // two 64-wide dots: 16 broadcast LDS.128, 64 FFMA2 over 8 accumulators
    const ulonglong2* s2 = (const ulonglong2*)se_read;
    ull a00 = 0ull, a01 = 0ull, a02 = 0ull, a03 = 0ull;
    ull a10 = 0ull, a11 = 0ull, a12 = 0ull, a13 = 0ull;
#pragma unroll
    for (int i = 0; i < 16; i += 2) {
        ulonglong2 qA = s2[i];
        ulonglong2 qB = s2[i + 1];
        asm("fma.rn.f32x2 %0, %1, %2, %0;" : "+l"(a00) : "l"(qA.x), "l"(Ep0[2 * i + 0]));
        asm("fma.rn.f32x2 %0, %1, %2, %0;" : "+l"(a10) : "l"(qA.x), "l"(Ep1[2 * i + 0]));
        asm("fma.rn.f32x2 %0, %1, %2, %0;" : "+l"(a01) : "l"(qA.y), "l"(Ep0[2 * i + 1]));
        asm("fma.rn.f32x2 %0, %1, %2, %0;" : "+l"(a11) : "l"(qA.y), "l"(Ep1[2 * i + 1]));
        asm("fma.rn.f32x2 %0, %1, %2, %0;" : "+l"(a02) : "l"(qB.x), "l"(Ep0[2 * i + 2]));
        asm("fma.rn.f32x2 %0, %1, %2, %0;" : "+l"(a12) : "l"(qB.x), "l"(Ep1[2 * i + 2]));
        asm("fma.rn.f32x2 %0, %1, %2, %0;" : "+l"(a03) : "l"(qB.y), "l"(Ep0[2 * i + 3]));
        asm("fma.rn.f32x2 %0, %1, %2, %0;" : "+l"(a13) : "l"(qB.y), "l"(Ep1[2 * i + 3]));
    }
    asm("add.rn.f32x2 %0, %0, %1;" : "+l"(a00) : "l"(a02));
    asm("add.rn.f32x2 %0, %0, %1;" : "+l"(a01) : "l"(a03));
    asm("add.rn.f32x2 %0, %0, %1;" : "+l"(a10) : "l"(a12));
    asm("add.rn.f32x2 %0, %0, %1;" : "+l"(a11) : "l"(a13));
    asm("add.rn.f32x2 %0, %0, %1;" : "+l"(a00) : "l"(a01));
    asm("add.rn.f32x2 %0, %0, %1;" : "+l"(a10) : "l"(a11));
    float v0l, v0h, v1l, v1h;
    asm("mov.b64 {%0, %1}, %2;" : "=f"(v0l), "=f"(v0h) : "l"(a00));
    asm("mov.b64 {%0, %1}, %2;" : "=f"(v1l), "=f"(v1h) : "l"(a10));

    const float sn0 = (v0l + v0h) * ma;
    const float sn1 = (v1l + v1h) * mb;
    ull pk;
    asm("mov.b64 %0, {%1, %2};" : "=l"(pk) : "f"(sn0), "f"(sn1));
    *(ull*)(se_write + 2 * l) = pk;
    s0prev = __shfl_sync(0xffffffffu, sn0, 0);
    __syncwarp();
}

// ---------------------------------------------------------------------------
// Fused kernel: threads 0-31 = forward chain (single warp, 2 cols/thread),
//               threads 32-63 = gold-path score warp. One block per batch.
// ---------------------------------------------------------------------------
__global__ __launch_bounds__(64) void crf_fused_kernel(
    const float* __restrict__ logits,   // [S, B, T]
    const void*  __restrict__ tags,     // [S, B] int32/int64 (detected)
    const float* __restrict__ trans,    // [T, T]
    const float* __restrict__ startt,   // [T]
    const float* __restrict__ endt)     // [T]
{
    const int b = blockIdx.x;
    const int tid = threadIdx.x;

    // ===================== score warp (threads 32-63) =====================
    if (tid >= 32) {
        const int lane = tid - 32;
        const int is64 = g_tags_is64;
        const int* mrow = &g_maskT[b * SEQ];
        float s = 0.f;
        int msum = 0;
        for (int t = lane; t < SEQ; t += 32) {
            const int tg = load_tag(tags, (size_t)t * BAT + b, is64);
            const int mt = mrow[t];
            msum += mt;
            if (t < SEQ - 1) {
                const int tgn = load_tag(tags, (size_t)(t + 1) * BAT + b, is64);
                const int mtn = mrow[t + 1];
                s += trans[tg * NTAG + tgn] * (float)mtn;
                s += logits[((size_t)t * BAT + b) * NTAG + tg] * (float)mt;
            }
        }
#pragma unroll
        for (int o = 16; o > 0; o >>= 1) {
            s += __shfl_xor_sync(0xffffffffu, s, o);
            msum += __shfl_xor_sync(0xffffffffu, msum, o);
        }
        if (lane == 0) {
            const int last_idx = msum - 1;
            const int last_tag = load_tag(tags, (size_t)last_idx * BAT + b, is64);
            const int tg0 = load_tag(tags, (size_t)b, is64);
            const float mlast = (float)mrow[SEQ - 1];
            g_score[b] = s + startt[tg0] + endt[last_tag]
                       + logits[((size_t)(SEQ - 1) * BAT + b) * NTAG + last_tag] * mlast;
        }
        return;
    }

    // ============ forward warp: lane l owns columns c0=2l, c1=2l+1 ============
    const int l = tid;
    const int c0 = 2 * l;
    const int c1 = c0 + 1;

    // E columns, packed row-pairs: Ep[p] = (exp(trans[2p][c]), exp(trans[2p+1][c]))
    ull Ep0[NTAG / 2], Ep1[NTAG / 2];
#pragma unroll
    for (int i = 0; i < NTAG / 2; i++) {
        float e00 = __expf(trans[(2 * i) * NTAG + c0]);
        float e01 = __expf(trans[(2 * i + 1) * NTAG + c0]);
        float e10 = __expf(trans[(2 * i) * NTAG + c1]);
        float e11 = __expf(trans[(2 * i + 1) * NTAG + c1]);
        asm("mov.b64 %0, {%1, %2};" : "=l"(Ep0[i]) : "f"(e00), "f"(e01));
        asm("mov.b64 %0, {%1, %2};" : "=l"(Ep1[i]) : "f"(e10), "f"(e11));
    }

    __shared__ __align__(16) float se[2][NTAG];

    const float a0 = startt[c0] + logits[(size_t)b * NTAG + c0];
    const float a1 = startt[c1] + logits[(size_t)b * NTAG + c1];
    const float m0 = __shfl_sync(0xffffffffu, a0, 0);

    const float* lptr = logits + (size_t)b * NTAG + c0;  // pair (c0,c1) contiguous

    if (g_mask_ones) {
        // ============== FAST PATH: pure linear-space recurrence ==============
        float s0i = __expf(a0 - m0);
        float s1i = __expf(a1 - m0);
        ull pk;
        asm("mov.b64 %0, {%1, %2};" : "=l"(pk) : "f"(s0i), "f"(s1i));
        *(ull*)(&se[0][c0]) = pk;
        float s0prev = __shfl_sync(0xffffffffu, s0i, 0);

        // prefetch ring, depth 4 (float2 = both columns)
        float2 raw[4];
#pragma unroll
        for (int u = 0; u < 4; u++)
            raw[u] = *(const float2*)(lptr + (size_t)(1 + u) * TSTRIDE);
        __syncwarp();   // se[0] visible

        int e_sum = 0;
        // steps k=0..1022 (t = k+1); main loop covers k=0..1019, remainder 3
        for (int t0 = 1; t0 + 3 <= SEQ - 3; t0 += 4) {
#pragma unroll
            for (int u = 0; u < 4; u++) {
                fast_step_w(se[u & 1], se[(u & 1) ^ 1], l, Ep0, Ep1,
                            raw[u], s0prev, e_sum);
                if (t0 + u + 4 <= SEQ - 1)
                    raw[u] = *(const float2*)(lptr + (size_t)(t0 + u + 4) * TSTRIDE);
            }
        }
        // remainder: t = 1021, 1022, 1023 (3 steps), parity continues (k even start)
#pragma unroll
        for (int u = 0; u < 3; u++)
            fast_step_w(se[u & 1], se[(u & 1) ^ 1], l, Ep0, Ep1,
                        raw[u], s0prev, e_sum);

        // final s pair for cols c0,c1 is in se[1] (last write) — read own pair
        ull fp = *(const ull*)(&se[1][c0]);
        float sf0, sf1;
        asm("mov.b64 {%0, %1}, %2;" : "=f"(sf0), "=f"(sf1) : "l"(fp));

        // logsumexp over 64 columns: x = m0 + e_sum*ln2 + log(s) + end
        const float base = m0 + (float)e_sum * LN2;
        float x0 = base + logf(sf0) + endt[c0];
        float x1 = base + logf(sf1) + endt[c1];
        float mm = fmaxf(x0, x1);
#pragma unroll
        for (int o = 16; o > 0; o >>= 1)
            mm = fmaxf(mm, __shfl_xor_sync(0xffffffffu, mm, o));
        float e = __expf(x0 - mm) + __expf(x1 - mm);
#pragma unroll
        for (int o = 16; o > 0; o >>= 1)
            e += __shfl_xor_sync(0xffffffffu, e, o);
        if (l == 0) g_denom[b] = mm + logf(e);
        return;
    }

    // ============== GENERAL PATH (mask not all ones): log-space ==============
    {
        float al0 = a0, al1 = a1;
        float m = m0;
        const int* mrow = &g_maskT[b * SEQ];
        float2 logit_next = *(const float2*)(lptr + (size_t)1 * TSTRIDE);

        for (int t = 1; t < SEQ; t++) {
            float* buf = se[t & 1];
            const float2 logit = logit_next;
            if (t + 1 < SEQ)
                logit_next = *(const float2*)(lptr + (size_t)(t + 1) * TSTRIDE);
            const int mk = mrow[t];

            float e0 = __expf(al0 - m);
            float e1 = __expf(al1 - m);
            ull pk;
            asm("mov.b64 %0, {%1, %2};" : "=l"(pk) : "f"(e0), "f"(e1));
            *(ull*)(buf + c0) = pk;
            __syncwarp();

            const ulonglong2* s2 = (const ulonglong2*)buf;
            ull q00 = 0ull, q01 = 0ull, q10 = 0ull, q11 = 0ull;
#pragma unroll
            for (int i = 0; i < 16; i++) {
                ulonglong2 q = s2[i];
                asm("fma.rn.f32x2 %0, %1, %2, %0;" : "+l"(q00) : "l"(q.x), "l"(Ep0[2 * i]));
                asm("fma.rn.f32x2 %0, %1, %2, %0;" : "+l"(q10) : "l"(q.x), "l"(Ep1[2 * i]));
                asm("fma.rn.f32x2 %0, %1, %2, %0;" : "+l"(q01) : "l"(q.y), "l"(Ep0[2 * i + 1]));
                asm("fma.rn.f32x2 %0, %1, %2, %0;" : "+l"(q11) : "l"(q.y), "l"(Ep1[2 * i + 1]));
            }
            asm("add.rn.f32x2 %0, %0, %1;" : "+l"(q00) : "l"(q01));
            asm("add.rn.f32x2 %0, %0, %1;" : "+l"(q10) : "l"(q11));
            float w0l, w0h, w1l, w1h;
            asm("mov.b64 {%0, %1}, %2;" : "=f"(w0l), "=f"(w0h) : "l"(q00));
            asm("mov.b64 {%0, %1}, %2;" : "=f"(w1l), "=f"(w1h) : "l"(q10));
            const float v0 = w0l + w0h;
            const float v1 = w1l + w1h;

            const float na0 = logit.x + m + __logf(v0);
            const float na1 = logit.y + m + __logf(v1);
            al0 = mk ? na0 : al0;
            al1 = mk ? na1 : al1;
            m = __shfl_sync(0xffffffffu, al0, 0);
            __syncwarp();
        }

        float x0 = al0 + endt[c0];
        float x1 = al1 + endt[c1];
        float mm = fmaxf(x0, x1);
#pragma unroll
        for (int o = 16; o > 0; o >>= 1)
            mm = fmaxf(mm, __shfl_xor_sync(0xffffffffu, mm, o));
        float e = __expf(x0 - mm) + __expf(x1 - mm);
#pragma unroll
        for (int o = 16; o > 0; o >>= 1)
            e += __shfl_xor_sync(0xffffffffu, e, o);
        if (l == 0) g_denom[b] = mm + logf(e);
    }
}

// ---------------------------------------------------------------------------
// Deterministic final reduction: out = sum_b (score_b - denom_b)
// ---------------------------------------------------------------------------
__global__ void crf_reduce_kernel(float* __restrict__ out) {
    __shared__ float sm[BAT];
    const int i = threadIdx.x;
    sm[i] = g_score[i] - g_denom[i];
    __syncthreads();
    for (int o = BAT / 2; o > 0; o >>= 1) {
        if (i < o) sm[i] += sm[i + o];
        __syncthreads();
    }
    if (i == 0) out[0] = sm[0];
}

// ---------------------------------------------------------------------------
extern "C" void kernel_launch(void* const* d_in, const int* in_sizes, int n_in,
                              void* d_out, int out_size) {
    const float* logits = (const float*)d_in[0];   // [S,B,T] f32
    const void*  tags   = d_in[1];                 // [S,B] i32 or i64
    const int*   mask   = (const int*)d_in[2];     // [S,B] i32
    const float* trans  = (const float*)d_in[3];   // [T,T]
    const float* startt = (const float*)d_in[4];   // [T]
    const float* endt   = (const float*)d_in[5];   // [T]
    float* out = (float*)d_out;

    detect_tags_kernel<<<1, 1>>>((const int*)tags);
    mask_transpose_kernel<<<(SEQ * BAT + 255) / 256, 256>>>(mask);
    crf_fused_kernel<<<BAT, 64>>>(logits, tags, trans, startt, endt);
    crf_reduce_kernel<<<1, BAT>>>(out);
}

// round 8
// speedup vs baseline: 1.9568x; 1.9568x over previous
#include <cuda_runtime.h>
#include <cuda_bf16.h>

// Problem shape (fixed for this bench problem)
#define SEQ  1024
#define BAT  512
#define NTAG 64
#define TSTRIDE (BAT * NTAG)
#define LN2 0.69314718055994531f
#define SE_STRIDE 68   // 32 + gap(4) + 32, bank-conflict-free halves

typedef unsigned long long ull;

// Scratch (device globals: allocation-free rule)
__device__ float g_denom[BAT];
__device__ float g_score[BAT];
__device__ int   g_maskT[BAT * SEQ];
__device__ int   g_tags_is64;
__device__ int   g_mask_ones;

// named barrier over the 4 forward warps (threads 0..127); score warp excluded
#define BAR1() asm volatile("bar.sync 1, 128;" ::: "memory")

// ---------------------------------------------------------------------------
__global__ void detect_tags_kernel(const int* __restrict__ tags32) {
    int is64 = 1;
    for (int i = 1; i < 128; i += 2)
        if (tags32[i] != 0) { is64 = 0; break; }
    g_tags_is64 = is64;
    g_mask_ones = 1;
}

__device__ __forceinline__ int load_tag(const void* tags, size_t idx, int is64) {
    if (is64) return (int)((const long long*)tags)[idx];
    return ((const int*)tags)[idx];
}

// ---------------------------------------------------------------------------
__global__ void mask_transpose_kernel(const int* __restrict__ mask) {
    int idx = blockIdx.x * blockDim.x + threadIdx.x;
    if (idx < SEQ * BAT) {
        int t = idx / BAT;
        int b = idx - t * BAT;
        int v = mask[idx];
        g_maskT[b * SEQ + t] = v;
        if (v != 1) g_mask_ones = 0;   // benign race: all writers store 0
    }
}

// ---------------------------------------------------------------------------
// Half-dot over 32 rows: 8 LDS.128 (broadcast) + 16 FFMA2, 4 accumulators.
// rdh points at this thread's 32-row half (16B aligned). All Ep indices literal.
// ---------------------------------------------------------------------------
__device__ __forceinline__ float half_dot(const float* __restrict__ rdh,
                                          const ull* __restrict__ Ep)
{
    const ulonglong2* s2 = (const ulonglong2*)rdh;
    ull a0 = 0ull, a1 = 0ull, a2 = 0ull, a3 = 0ull;
#pragma unroll
    for (int i = 0; i < 8; i += 2) {
        ulonglong2 qA = s2[i];
        ulonglong2 qB = s2[i + 1];
        asm("fma.rn.f32x2 %0, %1, %2, %0;" : "+l"(a0) : "l"(qA.x), "l"(Ep[2 * i + 0]));
        asm("fma.rn.f32x2 %0, %1, %2, %0;" : "+l"(a1) : "l"(qA.y), "l"(Ep[2 * i + 1]));
        asm("fma.rn.f32x2 %0, %1, %2, %0;" : "+l"(a2) : "l"(qB.x), "l"(Ep[2 * i + 2]));
        asm("fma.rn.f32x2 %0, %1, %2, %0;" : "+l"(a3) : "l"(qB.y), "l"(Ep[2 * i + 3]));
    }
    asm("add.rn.f32x2 %0, %0, %1;" : "+l"(a0) : "l"(a2));
    asm("add.rn.f32x2 %0, %0, %1;" : "+l"(a1) : "l"(a3));
    asm("add.rn.f32x2 %0, %0, %1;" : "+l"(a0) : "l"(a1));
    float lo, hi;
    asm("mov.b64 {%0, %1}, %2;" : "=f"(lo), "=f"(hi) : "l"(a0));
    return lo + hi;
}

// ---------------------------------------------------------------------------
// One linear-space step (fast path), 2 threads per column.
// Returns new s for this pair's column (valid on both threads).
// ---------------------------------------------------------------------------
__device__ __forceinline__ float fstep4(
    const float* __restrict__ rdh,   // this thread's half base
    const float* __restrict__ rd0,   // buffer base (s_0 broadcast)
    float* __restrict__ wr,          // write buffer base
    int pos, int isOdd,
    const ull* __restrict__ Ep, float rawv, int& e_sum)
{
    const float c = __expf(rawv);                 // MUFU, hidden under dot

    // renorm from s_0 (exact power of 2) — off critical path
    const float s0 = rd0[0];
    int ex = (__float_as_int(s0) >> 23) & 0xFF;
    ex = max(1, min(ex, 253));
    e_sum += ex - 127;
    const float rsc = __int_as_float((254 - ex) << 23);
    const float cmul = c * rsc;

    float partial = half_dot(rdh, Ep);
    const float total = partial + __shfl_xor_sync(0xffffffffu, partial, 1);
    const float snew = total * cmul;
    if (!isOdd) wr[pos] = snew;
    BAR1();
    return snew;
}

// ---------------------------------------------------------------------------
// Fused kernel: threads 0-127 = forward (4 warps, 2 threads/column),
//               threads 128-159 = gold-path score warp. One block per batch.
// ---------------------------------------------------------------------------
__global__ __launch_bounds__(160) void crf_fused_kernel(
    const float* __restrict__ logits,   // [S, B, T]
    const void*  __restrict__ tags,     // [S, B] int32/int64 (detected)
    const float* __restrict__ trans,    // [T, T]
    const float* __restrict__ startt,   // [T]
    const float* __restrict__ endt)     // [T]
{
    const int b = blockIdx.x;
    const int tid = threadIdx.x;

    // ===================== score warp (threads 128-159) =====================
    if (tid >= 128) {
        const int lane = tid - 128;
        const int is64 = g_tags_is64;
        const int* mrow = &g_maskT[b * SEQ];
        float s = 0.f;
        int msum = 0;
        for (int t = lane; t < SEQ; t += 32) {
            const int tg = load_tag(tags, (size_t)t * BAT + b, is64);
            const int mt = mrow[t];
            msum += mt;
            if (t < SEQ - 1) {
                const int tgn = load_tag(tags, (size_t)(t + 1) * BAT + b, is64);
                const int mtn = mrow[t + 1];
                s += trans[tg * NTAG + tgn] * (float)mtn;
                s += logits[((size_t)t * BAT + b) * NTAG + tg] * (float)mt;
            }
        }
#pragma unroll
        for (int o = 16; o > 0; o >>= 1) {
            s += __shfl_xor_sync(0xffffffffu, s, o);
            msum += __shfl_xor_sync(0xffffffffu, msum, o);
        }
        if (lane == 0) {
            const int last_idx = msum - 1;
            const int last_tag = load_tag(tags, (size_t)last_idx * BAT + b, is64);
            const int tg0 = load_tag(tags, (size_t)b, is64);
            const float mlast = (float)mrow[SEQ - 1];
            g_score[b] = s + startt[tg0] + endt[last_tag]
                       + logits[((size_t)(SEQ - 1) * BAT + b) * NTAG + last_tag] * mlast;
        }
        return;  // never touches named barrier 1
    }

    // ============== forward threads: pair (2c, 2c+1) owns column c ==========
    const int w = tid >> 5;          // warp 0..3
    const int l = tid & 31;
    const int c = tid >> 1;          // column 0..63
    const int h = tid & 1;           // 0: rows 0-31, 1: rows 32-63
    const int pos = c + ((c >> 5) << 2);   // gapped position of column c

    // Ep[i] = (exp(trans[32h+2i][c]), exp(trans[32h+2i+1][c])) — literal idx only
    ull Ep[16];
#pragma unroll
    for (int i = 0; i < 16; i++) {
        const int r = 32 * h + 2 * i;
        float e0 = __expf(trans[r * NTAG + c]);
        float e1 = __expf(trans[(r + 1) * NTAG + c]);
        asm("mov.b64 %0, {%1, %2};" : "=l"(Ep[i]) : "f"(e0), "f"(e1));
    }

    __shared__ __align__(16) float se[2][SE_STRIDE];
    __shared__ float aux[8];

    // this thread's read half bases for both buffers (byte offset 0 or 144)
    const float* rdh0 = &se[0][h * 36];
    const float* rdh1 = &se[1][h * 36];

    const float a0 = startt[c] + logits[(size_t)b * NTAG + c];
    if (tid == 0) aux[0] = a0;
    BAR1();
    const float m0 = aux[0];

    const float* lptr = logits + (size_t)b * NTAG + c;

    if (g_mask_ones) {
        // ============== FAST PATH: pure linear-space recurrence ==============
        if (!h) se[0][pos] = __expf(a0 - m0);

        // prefetch ring, depth 8 (pair-duplicated loads, L2-dedup'd)
        float raw[8];
#pragma unroll
        for (int u = 0; u < 8; u++)
            raw[u] = lptr[(size_t)(1 + u) * TSTRIDE];
        BAR1();   // se[0] visible

        float sj = 0.f;
        int e_sum = 0;
        for (int t0 = 1; t0 + 7 <= SEQ - 1; t0 += 8) {
#pragma unroll
            for (int u = 0; u < 8; u++) {
                sj = fstep4((u & 1) ? rdh1 : rdh0, se[u & 1], se[(u & 1) ^ 1],
                            pos, h, Ep, raw[u], e_sum);
                if (t0 + u + 8 <= SEQ - 1)
                    raw[u] = lptr[(size_t)(t0 + u + 8) * TSTRIDE];
            }
        }
        // remainder steps: t = 1017..1023 (7 steps)
#pragma unroll
        for (int u = 0; u < 7; u++)
            sj = fstep4((u & 1) ? rdh1 : rdh0, se[u & 1], se[(u & 1) ^ 1],
                        pos, h, Ep, raw[u], e_sum);

        // final logsumexp over 64 columns (even threads hold x, odd = -inf)
        float x = h ? -3.0e38f
                    : (m0 + (float)e_sum * LN2 + logf(sj) + endt[c]);
        float mm = x;
#pragma unroll
        for (int o = 16; o > 0; o >>= 1)
            mm = fmaxf(mm, __shfl_xor_sync(0xffffffffu, mm, o));
        if (l == 0) aux[w] = mm;
        BAR1();
        mm = fmaxf(fmaxf(aux[0], aux[1]), fmaxf(aux[2], aux[3]));
        float e = __expf(x - mm);   // odd threads contribute 0
#pragma unroll
        for (int o = 16; o > 0; o >>= 1)
            e += __shfl_xor_sync(0xffffffffu, e, o);
        if (l == 0) aux[4 + w] = e;
        BAR1();
        if (tid == 0)
            g_denom[b] = mm + logf(aux[4] + aux[5] + aux[6] + aux[7]);
        return;
    }

    // ============== GENERAL PATH (mask not all ones): log-space ==============
    {
        __shared__ float sm0[2];
        float alpha = a0;      // meaningful on even threads
        float m = m0;
        const int* mrow = &g_maskT[b * SEQ];
        float logit_next = lptr[(size_t)1 * TSTRIDE];

        for (int t = 1; t < SEQ; t++) {
            const int buf = t & 1;
            const float logit = logit_next;
            if (t + 1 < SEQ) logit_next = lptr[(size_t)(t + 1) * TSTRIDE];
            const int mk = mrow[t];

            if (!h) {
                se[buf][pos] = __expf(alpha - m);
                if (tid == 0) sm0[buf] = alpha;
            }
            BAR1();

            float partial = half_dot(buf ? rdh1 : rdh0, Ep);
            const float v = partial + __shfl_xor_sync(0xffffffffu, partial, 1);

            const float na = logit + m + __logf(v);
            alpha = mk ? na : alpha;
            m = sm0[buf];
        }

        float x = h ? -3.0e38f : (alpha + endt[c]);
        float mm = x;
#pragma unroll
        for (int o = 16; o > 0; o >>= 1)
            mm = fmaxf(mm, __shfl_xor_sync(0xffffffffu, mm, o));
        if (l == 0) aux[w] = mm;
        BAR1();
        mm = fmaxf(fmaxf(aux[0], aux[1]), fmaxf(aux[2], aux[3]));
        float e = __expf(x - mm);
#pragma unroll
        for (int o = 16; o > 0; o >>= 1)
            e += __shfl_xor_sync(0xffffffffu, e, o);
        if (l == 0) aux[4 + w] = e;
        BAR1();
        if (tid == 0)
            g_denom[b] = mm + logf(aux[4] + aux[5] + aux[6] + aux[7]);
    }
}

// ---------------------------------------------------------------------------
// Deterministic final reduction: out = sum_b (score_b - denom_b)
// ---------------------------------------------------------------------------
__global__ void crf_reduce_kernel(float* __restrict__ out) {
    __shared__ float sm[BAT];
    const int i = threadIdx.x;
    sm[i] = g_score[i] - g_denom[i];
    __syncthreads();
    for (int o = BAT / 2; o > 0; o >>= 1) {
        if (i < o) sm[i] += sm[i + o];
        __syncthreads();
    }
    if (i == 0) out[0] = sm[0];
}

// ---------------------------------------------------------------------------
extern "C" void kernel_launch(void* const* d_in, const int* in_sizes, int n_in,
                              void* d_out, int out_size) {
    const float* logits = (const float*)d_in[0];   // [S,B,T] f32
    const void*  tags   = d_in[1];                 // [S,B] i32 or i64
    const int*   mask   = (const int*)d_in[2];     // [S,B] i32
    const float* trans  = (const float*)d_in[3];   // [T,T]
    const float* startt = (const float*)d_in[4];   // [T]
    const float* endt   = (const float*)d_in[5];   // [T]
    float* out = (float*)d_out;

    detect_tags_kernel<<<1, 1>>>((const int*)tags);
    mask_transpose_kernel<<<(SEQ * BAT + 255) / 256, 256>>>(mask);
    crf_fused_kernel<<<BAT, 160>>>(logits, tags, trans, startt, endt);
    crf_reduce_kernel<<<1, BAT>>>(out);
}

// round 9
// speedup vs baseline: 1.9688x; 1.0061x over previous
#include <cuda_runtime.h>
#include <cuda_bf16.h>

// Problem shape (fixed for this bench problem)
#define SEQ  1024
#define BAT  512
#define NTAG 64
#define TSTRIDE (BAT * NTAG)
#define LN2 0.69314718055994531f
#define SE_STRIDE 68   // 32 + gap(4) + 32, bank-conflict-free halves

typedef unsigned long long ull;

// Scratch (device globals: allocation-free rule)
__device__ float g_denom[BAT];
__device__ float g_score[BAT];
__device__ int   g_maskT[BAT * SEQ];
__device__ int   g_tags_is64;
__device__ int   g_mask_ones;

// named barrier over the 4 forward warps (threads 0..127); score warp excluded
#define BAR1() asm volatile("bar.sync 1, 128;" ::: "memory")

// ---------------------------------------------------------------------------
__global__ void detect_tags_kernel(const int* __restrict__ tags32) {
    int is64 = 1;
    for (int i = 1; i < 128; i += 2)
        if (tags32[i] != 0) { is64 = 0; break; }
    g_tags_is64 = is64;
    g_mask_ones = 1;
}

__device__ __forceinline__ int load_tag(const void* tags, size_t idx, int is64) {
    if (is64) return (int)((const long long*)tags)[idx];
    return ((const int*)tags)[idx];
}

// ---------------------------------------------------------------------------
__global__ void mask_transpose_kernel(const int* __restrict__ mask) {
    int idx = blockIdx.x * blockDim.x + threadIdx.x;
    if (idx < SEQ * BAT) {
        int t = idx / BAT;
        int b = idx - t * BAT;
        int v = mask[idx];
        g_maskT[b * SEQ + t] = v;
        if (v != 1) g_mask_ones = 0;   // benign race: all writers store 0
    }
}

// ---------------------------------------------------------------------------
// Half-dot over 32 rows: 8 LDS.128 (broadcast) + 16 FFMA2, 4 accumulators.
// rdh points at this thread's 32-row half (16B aligned). All Ep indices literal.
// ---------------------------------------------------------------------------
__device__ __forceinline__ float half_dot(const float* __restrict__ rdh,
                                          const ull* __restrict__ Ep)
{
    const ulonglong2* s2 = (const ulonglong2*)rdh;
    ull a0 = 0ull, a1 = 0ull, a2 = 0ull, a3 = 0ull;
#pragma unroll
    for (int i = 0; i < 8; i += 2) {
        ulonglong2 qA = s2[i];
        ulonglong2 qB = s2[i + 1];
        asm("fma.rn.f32x2 %0, %1, %2, %0;" : "+l"(a0) : "l"(qA.x), "l"(Ep[2 * i + 0]));
        asm("fma.rn.f32x2 %0, %1, %2, %0;" : "+l"(a1) : "l"(qA.y), "l"(Ep[2 * i + 1]));
        asm("fma.rn.f32x2 %0, %1, %2, %0;" : "+l"(a2) : "l"(qB.x), "l"(Ep[2 * i + 2]));
        asm("fma.rn.f32x2 %0, %1, %2, %0;" : "+l"(a3) : "l"(qB.y), "l"(Ep[2 * i + 3]));
    }
    asm("add.rn.f32x2 %0, %0, %1;" : "+l"(a0) : "l"(a2));
    asm("add.rn.f32x2 %0, %0, %1;" : "+l"(a1) : "l"(a3));
    asm("add.rn.f32x2 %0, %0, %1;" : "+l"(a0) : "l"(a1));
    float lo, hi;
    asm("mov.b64 {%0, %1}, %2;" : "=f"(lo), "=f"(hi) : "l"(a0));
    return lo + hi;
}

// ---------------------------------------------------------------------------
// One linear-space step (fast path), 2 threads per column.
// Returns new s for this pair's column (valid on both threads).
// ---------------------------------------------------------------------------
__device__ __forceinline__ float fstep4(
    const float* __restrict__ rdh,   // this thread's half base
    const float* __restrict__ rd0,   // buffer base (s_0 broadcast)
    float* __restrict__ wr,          // write buffer base
    int pos, int isOdd,
    const ull* __restrict__ Ep, float rawv, int& e_sum)
{
    const float c = __expf(rawv);                 // MUFU, hidden under dot

    // renorm from s_0 (exact power of 2) — off critical path
    const float s0 = rd0[0];
    int ex = (__float_as_int(s0) >> 23) & 0xFF;
    ex = max(1, min(ex, 253));
    e_sum += ex - 127;
    const float rsc = __int_as_float((254 - ex) << 23);
    const float cmul = c * rsc;

    float partial = half_dot(rdh, Ep);
    const float total = partial + __shfl_xor_sync(0xffffffffu, partial, 1);
    const float snew = total * cmul;
    if (!isOdd) wr[pos] = snew;
    BAR1();
    return snew;
}

// ---------------------------------------------------------------------------
// Fused kernel: threads 0-127 = forward (4 warps, 2 threads/column),
//               threads 128-159 = gold-path score warp. One block per batch.
// ---------------------------------------------------------------------------
__global__ __launch_bounds__(160) void crf_fused_kernel(
    const float* __restrict__ logits,   // [S, B, T]
    const void*  __restrict__ tags,     // [S, B] int32/int64 (detected)
    const float* __restrict__ trans,    // [T, T]
    const float* __restrict__ startt,   // [T]
    const float* __restrict__ endt)     // [T]
{
    const int b = blockIdx.x;
    const int tid = threadIdx.x;

    // ===================== score warp (threads 128-159) =====================
    if (tid >= 128) {
        const int lane = tid - 128;
        const int is64 = g_tags_is64;
        const int* mrow = &g_maskT[b * SEQ];
        float s = 0.f;
        int msum = 0;
        for (int t = lane; t < SEQ; t += 32) {
            const int tg = load_tag(tags, (size_t)t * BAT + b, is64);
            const int mt = mrow[t];
            msum += mt;
            if (t < SEQ - 1) {
                const int tgn = load_tag(tags, (size_t)(t + 1) * BAT + b, is64);
                const int mtn = mrow[t + 1];
                s += trans[tg * NTAG + tgn] * (float)mtn;
                s += logits[((size_t)t * BAT + b) * NTAG + tg] * (float)mt;
            }
        }
#pragma unroll
        for (int o = 16; o > 0; o >>= 1) {
            s += __shfl_xor_sync(0xffffffffu, s, o);
            msum += __shfl_xor_sync(0xffffffffu, msum, o);
        }
        if (lane == 0) {
            const int last_idx = msum - 1;
            const int last_tag = load_tag(tags, (size_t)last_idx * BAT + b, is64);
            const int tg0 = load_tag(tags, (size_t)b, is64);
            const float mlast = (float)mrow[SEQ - 1];
            g_score[b] = s + startt[tg0] + endt[last_tag]
                       + logits[((size_t)(SEQ - 1) * BAT + b) * NTAG + last_tag] * mlast;
        }
        return;  // never touches named barrier 1
    }

    // ============== forward threads: pair (2c, 2c+1) owns column c ==========
    const int w = tid >> 5;          // warp 0..3
    const int l = tid & 31;
    const int c = tid >> 1;          // column 0..63
    const int h = tid & 1;           // 0: rows 0-31, 1: rows 32-63
    const int pos = c + ((c >> 5) << 2);   // gapped position of column c

    // Ep[i] = (exp(trans[32h+2i][c]), exp(trans[32h+2i+1][c])) — literal idx only
    ull Ep[16];
#pragma unroll
    for (int i = 0; i < 16; i++) {
        const int r = 32 * h + 2 * i;
        float e0 = __expf(trans[r * NTAG + c]);
        float e1 = __expf(trans[(r + 1) * NTAG + c]);
        asm("mov.b64 %0, {%1, %2};" : "=l"(Ep[i]) : "f"(e0), "f"(e1));
    }

    __shared__ __align__(16) float se[2][SE_STRIDE];
    __shared__ float aux[8];

    // this thread's read half bases for both buffers (byte offset 0 or 144)
    const float* rdh0 = &se[0][h * 36];
    const float* rdh1 = &se[1][h * 36];

    const float a0 = startt[c] + logits[(size_t)b * NTAG + c];
    if (tid == 0) aux[0] = a0;
    BAR1();
    const float m0 = aux[0];

    const float* lptr = logits + (size_t)b * NTAG + c;

    if (g_mask_ones) {
        // ============== FAST PATH: pure linear-space recurrence ==============
        if (!h) se[0][pos] = __expf(a0 - m0);

        // prefetch ring, depth 8 (pair-duplicated loads, L2-dedup'd)
        float raw[8];
#pragma unroll
        for (int u = 0; u < 8; u++)
            raw[u] = lptr[(size_t)(1 + u) * TSTRIDE];
        BAR1();   // se[0] visible

        float sj = 0.f;
        int e_sum = 0;
        for (int t0 = 1; t0 + 7 <= SEQ - 1; t0 += 8) {
#pragma unroll
            for (int u = 0; u < 8; u++) {
                sj = fstep4((u & 1) ? rdh1 : rdh0, se[u & 1], se[(u & 1) ^ 1],
                            pos, h, Ep, raw[u], e_sum);
                if (t0 + u + 8 <= SEQ - 1)
                    raw[u] = lptr[(size_t)(t0 + u + 8) * TSTRIDE];
            }
        }
        // remainder steps: t = 1017..1023 (7 steps)
#pragma unroll
        for (int u = 0; u < 7; u++)
            sj = fstep4((u & 1) ? rdh1 : rdh0, se[u & 1], se[(u & 1) ^ 1],
                        pos, h, Ep, raw[u], e_sum);

        // final logsumexp over 64 columns (even threads hold x, odd = -inf)
        float x = h ? -3.0e38f
                    : (m0 + (float)e_sum * LN2 + logf(sj) + endt[c]);
        float mm = x;
#pragma unroll
        for (int o = 16; o > 0; o >>= 1)
            mm = fmaxf(mm, __shfl_xor_sync(0xffffffffu, mm, o));
        if (l == 0) aux[w] = mm;
        BAR1();
        mm = fmaxf(fmaxf(aux[0], aux[1]), fmaxf(aux[2], aux[3]));
        float e = __expf(x - mm);   // odd threads contribute 0
#pragma unroll
        for (int o = 16; o > 0; o >>= 1)
            e += __shfl_xor_sync(0xffffffffu, e, o);
        if (l == 0) aux[4 + w] = e;
        BAR1();
        if (tid == 0)
            g_denom[b] = mm + logf(aux[4] + aux[5] + aux[6] + aux[7]);
        return;
    }

    // ============== GENERAL PATH (mask not all ones): log-space ==============
    {
        __shared__ float sm0[2];
        float alpha = a0;      // meaningful on even threads
        float m = m0;
        const int* mrow = &g_maskT[b * SEQ];
        float logit_next = lptr[(size_t)1 * TSTRIDE];

        for (int t = 1; t < SEQ; t++) {
            const int buf = t & 1;
            const float logit = logit_next;
            if (t + 1 < SEQ) logit_next = lptr[(size_t)(t + 1) * TSTRIDE];
            const int mk = mrow[t];

            if (!h) {
                se[buf][pos] = __expf(alpha - m);
                if (tid == 0) sm0[buf] = alpha;
            }
            BAR1();

            float partial = half_dot(buf ? rdh1 : rdh0, Ep);
            const float v = partial + __shfl_xor_sync(0xffffffffu, partial, 1);

            const float na = logit + m + __logf(v);
            alpha = mk ? na : alpha;
            m = sm0[buf];
        }

        float x = h ? -3.0e38f : (alpha + endt[c]);
        float mm = x;
#pragma unroll
        for (int o = 16; o > 0; o >>= 1)
            mm = fmaxf(mm, __shfl_xor_sync(0xffffffffu, mm, o));
        if (l == 0) aux[w] = mm;
        BAR1();
        mm = fmaxf(fmaxf(aux[0], aux[1]), fmaxf(aux[2], aux[3]));
        float e = __expf(x - mm);
#pragma unroll
        for (int o = 16; o > 0; o >>= 1)
            e += __shfl_xor_sync(0xffffffffu, e, o);
        if (l == 0) aux[4 + w] = e;
        BAR1();
        if (tid == 0)
            g_denom[b] = mm + logf(aux[4] + aux[5] + aux[6] + aux[7]);
    }
}

// ---------------------------------------------------------------------------
// Deterministic final reduction: out = sum_b (score_b - denom_b)
// ---------------------------------------------------------------------------
__global__ void crf_reduce_kernel(float* __restrict__ out) {
    __shared__ float sm[BAT];
    const int i = threadIdx.x;
    sm[i] = g_score[i] - g_denom[i];
    __syncthreads();
    for (int o = BAT / 2; o > 0; o >>= 1) {
        if (i < o) sm[i] += sm[i + o];
        __syncthreads();
    }
    if (i == 0) out[0] = sm[0];
}

// ---------------------------------------------------------------------------
extern "C" void kernel_launch(void* const* d_in, const int* in_sizes, int n_in,
                              void* d_out, int out_size) {
    const float* logits = (const float*)d_in[0];   // [S,B,T] f32
    const void*  tags   = d_in[1];                 // [S,B] i32 or i64
    const int*   mask   = (const int*)d_in[2];     // [S,B] i32
    const float* trans  = (const float*)d_in[3];   // [T,T]
    const float* startt = (const float*)d_in[4];   // [T]
    const float* endt   = (const float*)d_in[5];   // [T]
    float* out = (float*)d_out;

    detect_tags_kernel<<<1, 1>>>((const int*)tags);
    mask_transpose_kernel<<<(SEQ * BAT + 255) / 256, 256>>>(mask);
    crf_fused_kernel<<<BAT, 160>>>(logits, tags, trans, startt, endt);
    crf_reduce_kernel<<<1, BAT>>>(out);
}

// round 10
// speedup vs baseline: 2.2435x; 1.1395x over previous
#include <cuda_runtime.h>
#include <cuda_bf16.h>

// Problem shape (fixed for this bench problem)
#define SEQ  1024
#define BAT  512
#define NTAG 64
#define TSTRIDE (BAT * NTAG)
#define LN2 0.69314718055994531f

typedef unsigned long long ull;

// Scratch (device globals: allocation-free rule)
__device__ float g_denom[BAT];
__device__ float g_score[BAT];
__device__ int   g_maskT[BAT * SEQ];
__device__ int   g_tags_is64;
__device__ int   g_mask_ones;

// named barriers: 1 = forward pair (thr 0-63), 2 = backward pair (thr 64-127),
// 3 = combine (thr 0-127). Score warp (128-159) never touches any.
#define BAR1() asm volatile("bar.sync 1, 64;" ::: "memory")
#define BAR2() asm volatile("bar.sync 2, 64;" ::: "memory")
#define BAR3() asm volatile("bar.sync 3, 128;" ::: "memory")

// ---------------------------------------------------------------------------
__global__ void detect_tags_kernel(const int* __restrict__ tags32) {
    int is64 = 1;
    for (int i = 1; i < 128; i += 2)
        if (tags32[i] != 0) { is64 = 0; break; }
    g_tags_is64 = is64;
    g_mask_ones = 1;
}

__device__ __forceinline__ int load_tag(const void* tags, size_t idx, int is64) {
    if (is64) return (int)((const long long*)tags)[idx];
    return ((const int*)tags)[idx];
}

// ---------------------------------------------------------------------------
__global__ void mask_transpose_kernel(const int* __restrict__ mask) {
    int idx = blockIdx.x * blockDim.x + threadIdx.x;
    if (idx < SEQ * BAT) {
        int t = idx / BAT;
        int b = idx - t * BAT;
        int v = mask[idx];
        g_maskT[b * SEQ + t] = v;
        if (v != 1) g_mask_ones = 0;   // benign race: all writers store 0
    }
}

// ---------------------------------------------------------------------------
// 64-wide dot in packed f32x2: 16 LDS.128 (broadcast) + 32 FFMA2, 4 accums.
// ---------------------------------------------------------------------------
__device__ __forceinline__ float dot64(const float* __restrict__ rd,
                                       const ull* __restrict__ Ep)
{
    const ulonglong2* s2 = (const ulonglong2*)rd;
    ull a0 = 0ull, a1 = 0ull, a2 = 0ull, a3 = 0ull;
#pragma unroll
    for (int i = 0; i < 16; i += 2) {
        ulonglong2 qA = s2[i];
        ulonglong2 qB = s2[i + 1];
        asm("fma.rn.f32x2 %0, %1, %2, %0;" : "+l"(a0) : "l"(qA.x), "l"(Ep[2 * i + 0]));
        asm("fma.rn.f32x2 %0, %1, %2, %0;" : "+l"(a1) : "l"(qA.y), "l"(Ep[2 * i + 1]));
        asm("fma.rn.f32x2 %0, %1, %2, %0;" : "+l"(a2) : "l"(qB.x), "l"(Ep[2 * i + 2]));
        asm("fma.rn.f32x2 %0, %1, %2, %0;" : "+l"(a3) : "l"(qB.y), "l"(Ep[2 * i + 3]));
    }
    asm("add.rn.f32x2 %0, %0, %1;" : "+l"(a0) : "l"(a2));
    asm("add.rn.f32x2 %0, %0, %1;" : "+l"(a1) : "l"(a3));
    asm("add.rn.f32x2 %0, %0, %1;" : "+l"(a0) : "l"(a1));
    float lo, hi;
    asm("mov.b64 {%0, %1}, %2;" : "=f"(lo), "=f"(hi) : "l"(a0));
    return lo + hi;
}

// exact power-of-2 renorm factor from a broadcast value; accumulates exponent
__device__ __forceinline__ float renorm(float s0, int& e_sum) {
    int ex = (__float_as_int(s0) >> 23) & 0xFF;
    ex = max(1, min(ex, 253));
    e_sum += ex - 127;
    return __int_as_float((254 - ex) << 23);
}

// ---------------------------------------------------------------------------
// Forward linear-space step (identical structure to the R6 champion):
// snew_j = (sum_i s_i * E[i][j]) * exp(logit_j) * rsc
// ---------------------------------------------------------------------------
__device__ __forceinline__ float fstepF(
    const float* __restrict__ rd, float* __restrict__ wr, int j,
    const ull* __restrict__ Ep, float rawv, int& e_sum)
{
    const float c = __expf(rawv);                 // hidden under the dot
    const float rsc = renorm(rd[0], e_sum);
    const float cmul = c * rsc;
    const float snew = dot64(rd, Ep) * cmul;
    wr[j] = snew;
    BAR1();
    return snew;
}

// ---------------------------------------------------------------------------
// Backward step: u_new_j = (sum_i E[j][i] * (u_i * c_i)) * rsc
// Stores w = u*c, barrier, dot with E ROW j.
// ---------------------------------------------------------------------------
__device__ __forceinline__ float bstepB(
    float* __restrict__ buf, int j,
    const ull* __restrict__ Ep, float rawv, float u, int& e_sum)
{
    const float c = __expf(rawv);
    buf[j] = u * c;
    BAR2();
    const float rsc = renorm(buf[0], e_sum);
    return dot64(buf, Ep) * rsc;
}

// ---------------------------------------------------------------------------
// Fused kernel per batch: thr 0-63 forward half (t=1..512),
// thr 64-127 backward half (t=1023..513), thr 128-159 gold-path score.
// ---------------------------------------------------------------------------
__global__ __launch_bounds__(160) void crf_fused_kernel(
    const float* __restrict__ logits,   // [S, B, T]
    const void*  __restrict__ tags,     // [S, B] int32/int64 (detected)
    const float* __restrict__ trans,    // [T, T]
    const float* __restrict__ startt,   // [T]
    const float* __restrict__ endt)     // [T]
{
    const int b = blockIdx.x;
    const int tid = threadIdx.x;

    // ===================== score warp (threads 128-159) =====================
    if (tid >= 128) {
        const int lane = tid - 128;
        const int is64 = g_tags_is64;
        const int* mrow = &g_maskT[b * SEQ];
        float s = 0.f;
        int msum = 0;
        for (int t = lane; t < SEQ; t += 32) {
            const int tg = load_tag(tags, (size_t)t * BAT + b, is64);
            const int mt = mrow[t];
            msum += mt;
            if (t < SEQ - 1) {
                const int tgn = load_tag(tags, (size_t)(t + 1) * BAT + b, is64);
                const int mtn = mrow[t + 1];
                s += trans[tg * NTAG + tgn] * (float)mtn;
                s += logits[((size_t)t * BAT + b) * NTAG + tg] * (float)mt;
            }
        }
#pragma unroll
        for (int o = 16; o > 0; o >>= 1) {
            s += __shfl_xor_sync(0xffffffffu, s, o);
            msum += __shfl_xor_sync(0xffffffffu, msum, o);
        }
        if (lane == 0) {
            const int last_idx = msum - 1;
            const int last_tag = load_tag(tags, (size_t)last_idx * BAT + b, is64);
            const int tg0 = load_tag(tags, (size_t)b, is64);
            const float mlast = (float)mrow[SEQ - 1];
            g_score[b] = s + startt[tg0] + endt[last_tag]
                       + logits[((size_t)(SEQ - 1) * BAT + b) * NTAG + last_tag] * mlast;
        }
        return;
    }

    __shared__ __align__(16) float seF[2][NTAG];
    __shared__ __align__(16) float seB[2][NTAG];
    __shared__ float sm_u[NTAG];
    __shared__ float aux[4];
    __shared__ int   s_esB;

    // ============== GENERAL PATH (mask not all ones): R6-exact ==============
    if (!g_mask_ones) {
        if (tid >= 64) return;   // backward group idle; no shared barriers used
        const int j = tid;
        const int w = j >> 5;
        const int l = j & 31;

        ull Ep[NTAG / 2];
#pragma unroll
        for (int i = 0; i < NTAG / 2; i++) {
            float e0 = __expf(trans[(2 * i) * NTAG + j]);
            float e1 = __expf(trans[(2 * i + 1) * NTAG + j]);
            asm("mov.b64 %0, {%1, %2};" : "=l"(Ep[i]) : "f"(e0), "f"(e1));
        }

        float alpha = startt[j] + logits[(size_t)b * NTAG + j];
        if (j == 0) aux[0] = alpha;
        BAR1();
        float m = aux[0];

        const int* mrow = &g_maskT[b * SEQ];
        const float* lptr = logits + (size_t)b * NTAG + j;
        float logit_next = lptr[(size_t)1 * TSTRIDE];

        for (int t = 1; t < SEQ; t++) {
            float* buf = seF[t & 1];
            const float logit = logit_next;
            if (t + 1 < SEQ) logit_next = lptr[(size_t)(t + 1) * TSTRIDE];
            const int mk = mrow[t];

            buf[j] = __expf(alpha - m);
            if (j == 0) aux[1] = alpha;
            BAR1();

            const float v = dot64(buf, Ep);
            const float na = logit + m + __logf(v);
            alpha = mk ? na : alpha;
            m = aux[1];
            BAR1();
        }

        float x = alpha + endt[j];
        float mm = x;
#pragma unroll
        for (int o = 16; o > 0; o >>= 1)
            mm = fmaxf(mm, __shfl_xor_sync(0xffffffffu, mm, o));
        if (l == 0) aux[w] = mm;
        BAR1();
        mm = fmaxf(aux[0], aux[1]);
        float e = __expf(x - mm);
#pragma unroll
        for (int o = 16; o > 0; o >>= 1)
            e += __shfl_xor_sync(0xffffffffu, e, o);
        if (l == 0) aux[2 + w] = e;
        BAR1();
        if (j == 0) g_denom[b] = mm + logf(aux[2] + aux[3]);
        return;
    }

    // ===================== FAST PATH: split chain =====================
    if (tid < 64) {
        // -------- forward half: v = M_512 ... M_1 s_0 --------
        const int j = tid;
        const int w = j >> 5;
        const int l = j & 31;

        // E columns packed: Ep[i] = (exp(trans[2i][j]), exp(trans[2i+1][j]))
        ull Ep[NTAG / 2];
#pragma unroll
        for (int i = 0; i < NTAG / 2; i++) {
            float e0 = __expf(trans[(2 * i) * NTAG + j]);
            float e1 = __expf(trans[(2 * i + 1) * NTAG + j]);
            asm("mov.b64 %0, {%1, %2};" : "=l"(Ep[i]) : "f"(e0), "f"(e1));
        }

        const float alpha0 = startt[j] + logits[(size_t)b * NTAG + j];
        if (j == 0) aux[0] = alpha0;
        BAR1();
        const float m0 = aux[0];
        float sj = __expf(alpha0 - m0);
        seF[0][j] = sj;

        const float* lptr = logits + (size_t)b * NTAG + j;
        float raw[8];
#pragma unroll
        for (int u = 0; u < 8; u++)
            raw[u] = lptr[(size_t)(1 + u) * TSTRIDE];
        BAR1();   // seF[0] visible

        int esF = 0;
        // 512 steps: t = 1..512, exactly 64 groups of 8
        for (int t0 = 1; t0 + 7 <= 512; t0 += 8) {
#pragma unroll
            for (int u = 0; u < 8; u++) {
                sj = fstepF(seF[u & 1], seF[(u & 1) ^ 1], j, Ep, raw[u], esF);
                if (t0 + u + 8 <= 512)
                    raw[u] = lptr[(size_t)(t0 + u + 8) * TSTRIDE];
            }
        }

        // -------- combine with backward half --------
        BAR3();   // sm_u, s_esB ready
        float p = sj * sm_u[j];
#pragma unroll
        for (int o = 16; o > 0; o >>= 1)
            p += __shfl_xor_sync(0xffffffffu, p, o);
        if (l == 0) aux[w] = p;
        BAR1();
        if (j == 0)
            g_denom[b] = m0 + (float)(esF + s_esB) * LN2 + logf(aux[0] + aux[1]);
        return;
    }

    // -------- backward half: u^T = e_end^T M_1023 ... M_513 --------
    {
        const int j = tid - 64;

        // E ROWS packed: Ep[i] = (exp(trans[j][2i]), exp(trans[j][2i+1]))
        ull Ep[NTAG / 2];
#pragma unroll
        for (int i = 0; i < NTAG / 2; i++) {
            float e0 = __expf(trans[j * NTAG + 2 * i]);
            float e1 = __expf(trans[j * NTAG + 2 * i + 1]);
            asm("mov.b64 %0, {%1, %2};" : "=l"(Ep[i]) : "f"(e0), "f"(e1));
        }

        float u_val = __expf(endt[j]);

        const float* lptr = logits + (size_t)b * NTAG + j;
        float raw[8];
#pragma unroll
        for (int u = 0; u < 8; u++)
            raw[u] = lptr[(size_t)(1023 - u) * TSTRIDE];

        int esB = 0;
        // 511 steps: k = 0..510 (t = 1023-k down to 513). Main: k = 0..503.
        for (int k0 = 0; k0 + 7 <= 503; k0 += 8) {
#pragma unroll
            for (int u = 0; u < 8; u++) {
                u_val = bstepB(seB[u & 1], j, Ep, raw[u], u_val, esB);
                if (k0 + u + 8 <= 510)
                    raw[u] = lptr[(size_t)(1023 - (k0 + u + 8)) * TSTRIDE];
            }
        }
        // remainder: k = 504..510 (7 steps)
#pragma unroll
        for (int u = 0; u < 7; u++)
            u_val = bstepB(seB[u & 1], j, Ep, raw[u], u_val, esB);

        sm_u[j] = u_val;
        if (j == 0) s_esB = esB;
        BAR3();
        return;
    }
}

// ---------------------------------------------------------------------------
// Deterministic final reduction: out = sum_b (score_b - denom_b)
// ---------------------------------------------------------------------------
__global__ void crf_reduce_kernel(float* __restrict__ out) {
    __shared__ float sm[BAT];
    const int i = threadIdx.x;
    sm[i] = g_score[i] - g_denom[i];
    __syncthreads();
    for (int o = BAT / 2; o > 0; o >>= 1) {
        if (i < o) sm[i] += sm[i + o];
        __syncthreads();
    }
    if (i == 0) out[0] = sm[0];
}

// ---------------------------------------------------------------------------
extern "C" void kernel_launch(void* const* d_in, const int* in_sizes, int n_in,
                              void* d_out, int out_size) {
    const float* logits = (const float*)d_in[0];   // [S,B,T] f32
    const void*  tags   = d_in[1];                 // [S,B] i32 or i64
    const int*   mask   = (const int*)d_in[2];     // [S,B] i32
    const float* trans  = (const float*)d_in[3];   // [T,T]
    const float* startt = (const float*)d_in[4];   // [T]
    const float* endt   = (const float*)d_in[5];   // [T]
    float* out = (float*)d_out;

    detect_tags_kernel<<<1, 1>>>((const int*)tags);
    mask_transpose_kernel<<<(SEQ * BAT + 255) / 256, 256>>>(mask);
    crf_fused_kernel<<<BAT, 160>>>(logits, tags, trans, startt, endt);
    crf_reduce_kernel<<<1, BAT>>>(out);
}